// round 16
// baseline (speedup 1.0000x reference)
#include <cuda_runtime.h>
#include <cstdint>

#define MAX_SEG 100001

// scratch (no cudaMalloc allowed)
__device__ int g_offsets[MAX_SEG + 1];

// ---------------------------------------------------------------------------
// Packed-f32 helpers (sm_103a f32x2 pipe) + raw 128-bit global load.
// ---------------------------------------------------------------------------
struct U2 { unsigned long long lo, hi; };

__device__ __forceinline__ U2 ldg_b128(const void* p) {
    U2 r;
    asm volatile("ld.global.nc.v2.u64 {%0,%1}, [%2];"
                 : "=l"(r.lo), "=l"(r.hi) : "l"(p));
    return r;
}
__device__ __forceinline__ unsigned long long addf32x2(unsigned long long a,
                                                       unsigned long long b) {
    unsigned long long r;
    asm("add.rn.f32x2 %0, %1, %2;" : "=l"(r) : "l"(a), "l"(b));
    return r;
}

// ---------------------------------------------------------------------------
// Inline dtype detection (reference declares int64; JAX w/o x64 emits int32).
// For little-endian int64 indices in [0, 2^31), every odd int32 word is 0.
// For int32 data those words are uniform random gather indices;
// P(first 8 all zero) ~ 1e-42.
// ---------------------------------------------------------------------------
__device__ __forceinline__ bool detect_is64_warp(const void* gidx, int lane) {
    const int* p = (const int*)gidx;
    int w = (lane < 8) ? p[2 * lane + 1] : 0;
    return __all_sync(0xFFFFFFFFu, w == 0);
}

__device__ __forceinline__ int load_idx(const void* p, int i, bool is64) {
    return is64 ? (int)((const long long*)p)[i] : ((const int*)p)[i];
}

// ---------------------------------------------------------------------------
// CSR offsets from sorted segment ids. offsets[s] = first edge with seg >= s.
// Each thread owns 8 consecutive edges (2x int4 / 4x longlong2 loads);
// seg[e0-1] comes from the neighbor lane's last element via shfl_up.
// ---------------------------------------------------------------------------
__global__ void __launch_bounds__(256)
build_offsets_kernel(const void* __restrict__ seg,
                     const void* __restrict__ gidx,
                     int E, int nseg) {
    int t    = blockIdx.x * blockDim.x + threadIdx.x;
    int lane = threadIdx.x & 31;
    bool is64 = detect_is64_warp(gidx, lane);

    int e0 = t * 8;
    int v[8];
    if (e0 + 8 <= E) {
        if (is64) {
            const longlong2* p = (const longlong2*)((const long long*)seg + e0);
            longlong2 a = p[0], b = p[1], c = p[2], d = p[3];
            v[0] = (int)a.x; v[1] = (int)a.y; v[2] = (int)b.x; v[3] = (int)b.y;
            v[4] = (int)c.x; v[5] = (int)c.y; v[6] = (int)d.x; v[7] = (int)d.y;
        } else {
            const int4* p = (const int4*)((const int*)seg + e0);
            int4 a = p[0], b = p[1];
            v[0] = a.x; v[1] = a.y; v[2] = a.z; v[3] = a.w;
            v[4] = b.x; v[5] = b.y; v[6] = b.z; v[7] = b.w;
        }
    } else {
        int eL = E - 1;
        #pragma unroll
        for (int k = 0; k < 8; k++)
            v[k] = load_idx(seg, e0 + k < E ? e0 + k : eL, is64);
    }

    int prev0 = __shfl_up_sync(0xFFFFFFFFu, v[7], 1);
    if (lane == 0) prev0 = (e0 == 0) ? -1 : load_idx(seg, e0 - 1, is64);
    if (e0 >= E) return;

    int prev = prev0;
    #pragma unroll
    for (int k = 0; k < 8; k++) {
        int e = e0 + k;
        if (e >= E) break;
        for (int s = prev + 1; s <= v[k]; s++) g_offsets[s] = e;
        if (e == E - 1) {
            for (int s = v[k] + 1; s <= nseg; s++) g_offsets[s] = E;
        }
        prev = v[k];
    }
}

// ---------------------------------------------------------------------------
// Warp-autonomous: TWO consecutive segments per warp, processed sequentially.
// Lanes 0-2 fetch the pair's three offsets in one sector. If the combined
// edge count fits one 32-index chunk (~90% of pairs), ONE coalesced index
// load serves both segments (saves a serial L2 round-trip + a prologue).
// Row loop: lane l16=lane&15 owns a float4 slot of the 256B row, half=lane>>4
// picks row e+half of an edge PAIR -> one LDG.128 fetches TWO gathered rows.
// Indices arrive via register shuffles. Halves combined with 4 shfl_xor(16).
// Segment 0's store overlaps segment 1's loads. No smem, no barriers.
// ---------------------------------------------------------------------------
__global__ void __launch_bounds__(128)
seg_mean_kernel(const float* __restrict__ values,
                const void* __restrict__ gidx,
                float* __restrict__ out, int nseg) {
    int tid  = threadIdx.x;
    int lane = tid & 31;
    int wid  = (blockIdx.x * 128 + tid) >> 5;
    int s0   = wid * 2;
    if (s0 >= nseg) return;

    bool is64 = detect_is64_warp(gidx, lane);
    bool has1 = (s0 + 1) < nseg;

    // three offsets with one coalesced sector load
    int off = 0;
    int oi = s0 + lane;
    if (lane < 3) off = g_offsets[oi <= nseg ? oi : nseg];
    int start0 = __shfl_sync(0xFFFFFFFFu, off, 0);
    int mid    = __shfl_sync(0xFFFFFFFFu, off, 1);
    int end1   = __shfl_sync(0xFFFFFFFFu, off, 2);
    if (!has1) end1 = mid;
    int ntot = end1 - start0;

    int half = lane >> 4;                // which row of the pair
    int l16  = lane & 15;                // float4 slot within row
    const char* vb = (const char*)values + l16 * 16;

    bool fastAll = (ntot <= 32);         // warp-uniform
    int myidx = 0;
    if (fastAll && lane < ntot)
        myidx = load_idx(gidx, start0 + lane, is64);

    for (int k = 0; k < 2; k++) {
        if (k && !has1) break;
        int st = k ? mid  : start0;
        int en = k ? end1 : mid;
        int n  = en - st;
        int sg = s0 + k;

        U2 A0; A0.lo = 0ull; A0.hi = 0ull;
        U2 A1; A1.lo = 0ull; A1.hi = 0ull;

        if (fastAll) {
            int base = st - start0;
            int j = 0;
            for (; j + 4 <= n; j += 4) {
                int ia = __shfl_sync(0xFFFFFFFFu, myidx, base + j + half);
                int ib = __shfl_sync(0xFFFFFFFFu, myidx, base + j + 2 + half);
                U2 va = ldg_b128(vb + (unsigned)ia * 256u);
                U2 vc = ldg_b128(vb + (unsigned)ib * 256u);
                A0.lo = addf32x2(A0.lo, va.lo); A0.hi = addf32x2(A0.hi, va.hi);
                A1.lo = addf32x2(A1.lo, vc.lo); A1.hi = addf32x2(A1.hi, vc.hi);
            }
            if (j + 2 <= n) {
                int ia = __shfl_sync(0xFFFFFFFFu, myidx, base + j + half);
                U2 va = ldg_b128(vb + (unsigned)ia * 256u);
                A0.lo = addf32x2(A0.lo, va.lo); A0.hi = addf32x2(A0.hi, va.hi);
                j += 2;
            }
            if (j < n) {
                int ia = __shfl_sync(0xFFFFFFFFu, myidx, base + j);
                U2 va = ldg_b128(vb + (unsigned)ia * 256u);
                if (half == 0) {
                    A0.lo = addf32x2(A0.lo, va.lo); A0.hi = addf32x2(A0.hi, va.hi);
                }
            }
        } else {
            for (int cb = 0; cb < n; cb += 32) {
                int m = n - cb;
                if (m > 32) m = 32;
                int mi = 0;
                if (lane < m) mi = load_idx(gidx, st + cb + lane, is64);

                int j = 0;
                for (; j + 4 <= m; j += 4) {
                    int ia = __shfl_sync(0xFFFFFFFFu, mi, j + half);
                    int ib = __shfl_sync(0xFFFFFFFFu, mi, j + 2 + half);
                    U2 va = ldg_b128(vb + (unsigned)ia * 256u);
                    U2 vc = ldg_b128(vb + (unsigned)ib * 256u);
                    A0.lo = addf32x2(A0.lo, va.lo); A0.hi = addf32x2(A0.hi, va.hi);
                    A1.lo = addf32x2(A1.lo, vc.lo); A1.hi = addf32x2(A1.hi, vc.hi);
                }
                if (j + 2 <= m) {
                    int ia = __shfl_sync(0xFFFFFFFFu, mi, j + half);
                    U2 va = ldg_b128(vb + (unsigned)ia * 256u);
                    A0.lo = addf32x2(A0.lo, va.lo); A0.hi = addf32x2(A0.hi, va.hi);
                    j += 2;
                }
                if (j < m) {
                    int ia = __shfl_sync(0xFFFFFFFFu, mi, j);
                    U2 va = ldg_b128(vb + (unsigned)ia * 256u);
                    if (half == 0) {
                        A0.lo = addf32x2(A0.lo, va.lo); A0.hi = addf32x2(A0.hi, va.hi);
                    }
                }
            }
        }

        unsigned long long Slo = addf32x2(A0.lo, A1.lo);
        unsigned long long Shi = addf32x2(A0.hi, A1.hi);

        float f0 = __uint_as_float((unsigned)(Slo & 0xFFFFFFFFull));
        float f1 = __uint_as_float((unsigned)(Slo >> 32));
        float f2 = __uint_as_float((unsigned)(Shi & 0xFFFFFFFFull));
        float f3 = __uint_as_float((unsigned)(Shi >> 32));

        // combine the two halves (same l16 slot, xor lane bit 4)
        f0 += __shfl_xor_sync(0xFFFFFFFFu, f0, 16);
        f1 += __shfl_xor_sync(0xFFFFFFFFu, f1, 16);
        f2 += __shfl_xor_sync(0xFFFFFFFFu, f2, 16);
        f3 += __shfl_xor_sync(0xFFFFFFFFu, f3, 16);

        float inv = 1.0f / (float)(n > 0 ? n : 1);
        if (half == 0) {
            float4 r = {f0 * inv, f1 * inv, f2 * inv, f3 * inv};
            ((float4*)(out + (long long)sg * 64))[l16] = r;
        }
    }
}

// ---------------------------------------------------------------------------
// launch
// inputs: 0=values [N_SRC,64] f32, 1=gather_idx [E] i64/i32,
//         2=segment_ids [E] i64/i32 (sorted), 3=num_segments (scalar, unused)
// out: [nseg,64] f32, nseg = out_size/64
// ---------------------------------------------------------------------------
extern "C" void kernel_launch(void* const* d_in, const int* in_sizes, int n_in,
                              void* d_out, int out_size) {
    const float* values = (const float*)d_in[0];
    const void*  gidx   = d_in[1];
    const void*  seg    = d_in[2];
    float* out = (float*)d_out;

    int E    = in_sizes[1];
    int nseg = out_size / 64;
    if (nseg > MAX_SEG) nseg = MAX_SEG;

    int bthreads = 256;
    int bwork = (E + 7) / 8;
    build_offsets_kernel<<<(bwork + bthreads - 1) / bthreads, bthreads>>>(seg, gidx, E, nseg);

    int npairs = (nseg + 1) / 2;
    int warps_per_block = 4;
    int blocks = (npairs + warps_per_block - 1) / warps_per_block;
    seg_mean_kernel<<<blocks, 128>>>(values, gidx, out, nseg);
}

// round 17
// speedup vs baseline: 1.0389x; 1.0389x over previous
#include <cuda_runtime.h>
#include <cstdint>

#define MAX_SEG 100001

// scratch (no cudaMalloc allowed)
__device__ int g_offsets[MAX_SEG + 1];

// ---------------------------------------------------------------------------
// Packed-f32 helpers (sm_103a f32x2 pipe) + raw 128-bit global load.
// ---------------------------------------------------------------------------
struct U2 { unsigned long long lo, hi; };

__device__ __forceinline__ U2 ldg_b128(const void* p) {
    U2 r;
    asm volatile("ld.global.nc.v2.u64 {%0,%1}, [%2];"
                 : "=l"(r.lo), "=l"(r.hi) : "l"(p));
    return r;
}
__device__ __forceinline__ unsigned long long addf32x2(unsigned long long a,
                                                       unsigned long long b) {
    unsigned long long r;
    asm("add.rn.f32x2 %0, %1, %2;" : "=l"(r) : "l"(a), "l"(b));
    return r;
}

// ---------------------------------------------------------------------------
// Inline dtype detection (reference declares int64; JAX w/o x64 emits int32).
// For little-endian int64 indices in [0, 2^31), every odd int32 word is 0.
// For int32 data those words are uniform random gather indices;
// P(first 8 all zero) ~ 1e-42.
// ---------------------------------------------------------------------------
__device__ __forceinline__ bool detect_is64_warp(const void* gidx, int lane) {
    const int* p = (const int*)gidx;
    int w = (lane < 8) ? p[2 * lane + 1] : 0;
    return __all_sync(0xFFFFFFFFu, w == 0);
}

__device__ __forceinline__ int load_idx(const void* p, int i, bool is64) {
    return is64 ? (int)((const long long*)p)[i] : ((const int*)p)[i];
}

// ---------------------------------------------------------------------------
// CSR offsets from sorted segment ids. offsets[s] = first edge with seg >= s.
// Each thread owns 8 consecutive edges (2x int4 / 4x longlong2 loads);
// seg[e0-1] comes from the neighbor lane's last element via shfl_up.
// ---------------------------------------------------------------------------
__global__ void __launch_bounds__(256)
build_offsets_kernel(const void* __restrict__ seg,
                     const void* __restrict__ gidx,
                     int E, int nseg) {
    int t    = blockIdx.x * blockDim.x + threadIdx.x;
    int lane = threadIdx.x & 31;
    bool is64 = detect_is64_warp(gidx, lane);

    int e0 = t * 8;
    int v[8];
    if (e0 + 8 <= E) {
        if (is64) {
            const longlong2* p = (const longlong2*)((const long long*)seg + e0);
            longlong2 a = p[0], b = p[1], c = p[2], d = p[3];
            v[0] = (int)a.x; v[1] = (int)a.y; v[2] = (int)b.x; v[3] = (int)b.y;
            v[4] = (int)c.x; v[5] = (int)c.y; v[6] = (int)d.x; v[7] = (int)d.y;
        } else {
            const int4* p = (const int4*)((const int*)seg + e0);
            int4 a = p[0], b = p[1];
            v[0] = a.x; v[1] = a.y; v[2] = a.z; v[3] = a.w;
            v[4] = b.x; v[5] = b.y; v[6] = b.z; v[7] = b.w;
        }
    } else {
        int eL = E - 1;
        #pragma unroll
        for (int k = 0; k < 8; k++)
            v[k] = load_idx(seg, e0 + k < E ? e0 + k : eL, is64);
    }

    int prev0 = __shfl_up_sync(0xFFFFFFFFu, v[7], 1);
    if (lane == 0) prev0 = (e0 == 0) ? -1 : load_idx(seg, e0 - 1, is64);
    if (e0 >= E) return;

    int prev = prev0;
    #pragma unroll
    for (int k = 0; k < 8; k++) {
        int e = e0 + k;
        if (e >= E) break;
        for (int s = prev + 1; s <= v[k]; s++) g_offsets[s] = e;
        if (e == E - 1) {
            for (int s = v[k] + 1; s <= nseg; s++) g_offsets[s] = E;
        }
        prev = v[k];
    }
}

// ---------------------------------------------------------------------------
// Warp-autonomous segmented mean: one warp per segment, NO smem, NO barriers.
// Offsets arrive via two parallel broadcast loads (L2-hot, shared across the
// 8 warps touching each sector) — no shuffles on the critical path. Each
// 32-edge chunk: one coalesced index load (gidx[start+lane]), then the pair
// loop — lane l16=lane&15 owns a float4 slot of the 256B row, half=lane>>4
// picks row e+half of an edge PAIR, so one LDG.128 fetches TWO gathered
// rows. Indices come from register shuffles. Halves combined with 4
// shfl_xor(16).
// ---------------------------------------------------------------------------
__global__ void __launch_bounds__(256)
seg_mean_kernel(const float* __restrict__ values,
                const void* __restrict__ gidx,
                float* __restrict__ out, int nseg) {
    int tid  = threadIdx.x;
    int lane = tid & 31;
    int seg  = (blockIdx.x * 256 + tid) >> 5;
    if (seg >= nseg) return;

    bool is64 = detect_is64_warp(gidx, lane);

    // both offsets via parallel broadcast loads (no shuffle on critical path)
    int start = g_offsets[seg];
    int end   = g_offsets[seg + 1];
    int n     = end - start;

    int half = lane >> 4;                // which row of the pair
    int l16  = lane & 15;                // float4 slot within row
    const char* vb = (const char*)values + l16 * 16;

    U2 A0; A0.lo = 0ull; A0.hi = 0ull;
    U2 A1; A1.lo = 0ull; A1.hi = 0ull;

    for (int base = 0; base < n; base += 32) {
        int m = n - base;
        if (m > 32) m = 32;
        // one coalesced load of up to 32 indices for this chunk
        int myidx = 0;
        if (lane < m) myidx = load_idx(gidx, start + base + lane, is64);

        int j = 0;
        // main: 4 edges (2 pairs) per iteration
        for (; j + 4 <= m; j += 4) {
            int ia = __shfl_sync(0xFFFFFFFFu, myidx, j + half);
            int ib = __shfl_sync(0xFFFFFFFFu, myidx, j + 2 + half);
            U2 va = ldg_b128(vb + (unsigned)ia * 256u);
            U2 vc = ldg_b128(vb + (unsigned)ib * 256u);
            A0.lo = addf32x2(A0.lo, va.lo); A0.hi = addf32x2(A0.hi, va.hi);
            A1.lo = addf32x2(A1.lo, vc.lo); A1.hi = addf32x2(A1.hi, vc.hi);
        }
        // one remaining pair
        if (j + 2 <= m) {
            int ia = __shfl_sync(0xFFFFFFFFu, myidx, j + half);
            U2 va = ldg_b128(vb + (unsigned)ia * 256u);
            A0.lo = addf32x2(A0.lo, va.lo); A0.hi = addf32x2(A0.hi, va.hi);
            j += 2;
        }
        // single remaining edge: only half 0 contributes
        if (j < m) {
            int ia = __shfl_sync(0xFFFFFFFFu, myidx, j);
            U2 va = ldg_b128(vb + (unsigned)ia * 256u);
            if (half == 0) {
                A0.lo = addf32x2(A0.lo, va.lo); A0.hi = addf32x2(A0.hi, va.hi);
            }
        }
    }

    unsigned long long Slo = addf32x2(A0.lo, A1.lo);
    unsigned long long Shi = addf32x2(A0.hi, A1.hi);

    float f0 = __uint_as_float((unsigned)(Slo & 0xFFFFFFFFull));
    float f1 = __uint_as_float((unsigned)(Slo >> 32));
    float f2 = __uint_as_float((unsigned)(Shi & 0xFFFFFFFFull));
    float f3 = __uint_as_float((unsigned)(Shi >> 32));

    // combine the two halves (same l16 slot, xor lane bit 4)
    f0 += __shfl_xor_sync(0xFFFFFFFFu, f0, 16);
    f1 += __shfl_xor_sync(0xFFFFFFFFu, f1, 16);
    f2 += __shfl_xor_sync(0xFFFFFFFFu, f2, 16);
    f3 += __shfl_xor_sync(0xFFFFFFFFu, f3, 16);

    float inv = 1.0f / (float)(n > 0 ? n : 1);
    if (half == 0) {
        float4 r = {f0 * inv, f1 * inv, f2 * inv, f3 * inv};
        ((float4*)(out + (long long)seg * 64))[l16] = r;
    }
}

// ---------------------------------------------------------------------------
// launch
// inputs: 0=values [N_SRC,64] f32, 1=gather_idx [E] i64/i32,
//         2=segment_ids [E] i64/i32 (sorted), 3=num_segments (scalar, unused)
// out: [nseg,64] f32, nseg = out_size/64
// ---------------------------------------------------------------------------
extern "C" void kernel_launch(void* const* d_in, const int* in_sizes, int n_in,
                              void* d_out, int out_size) {
    const float* values = (const float*)d_in[0];
    const void*  gidx   = d_in[1];
    const void*  seg    = d_in[2];
    float* out = (float*)d_out;

    int E    = in_sizes[1];
    int nseg = out_size / 64;
    if (nseg > MAX_SEG) nseg = MAX_SEG;

    int bthreads = 256;
    int bwork = (E + 7) / 8;
    build_offsets_kernel<<<(bwork + bthreads - 1) / bthreads, bthreads>>>(seg, gidx, E, nseg);

    int warps_per_block = 8;
    int blocks = (nseg + warps_per_block - 1) / warps_per_block;
    seg_mean_kernel<<<blocks, 256>>>(values, gidx, out, nseg);
}